// round 15
// baseline (speedup 1.0000x reference)
#include <cuda_runtime.h>
#include <cuda_fp8.h>
#include <cuda_fp16.h>
#include <cstdint>
#include <math.h>

// ---------------- problem constants ----------------
#define NQ     4096
#define NM     100000
#define D      128
#define NCH    37
#define CHUNK  2703          // ceil(NM / NCH)
#define QT     128           // queries per CTA (block M)
#define NT     128           // memory rows per tile (block N)
#define KC     8             // candidates kept per (query, chunk)

#define A_BYTES   (QT * D)              // fp8: 16384
#define B_BYTES   (NT * D)              // 16384
#define SMEM_DYN  (A_BYTES + 2 * B_BYTES + 1024)   // ~50KB

// ---------------- device scratch ----------------
__device__ float     g_qn[NQ * D];        // normalized queries (fp32)
__device__ uint32_t  g_qf8[NQ * 32];      // normalized queries (e4m3, 4/word)
__device__ uint32_t  g_mf8[NM * 32];      // normalized memory (e4m3)
__device__ float     g_invm[NM];          // 1/||m||
__device__ int       g_ci[NQ * NCH * KC];
__device__ int       g_dummy;

// ---------------- PTX helpers ----------------
__device__ __forceinline__ uint32_t s2u(const void* p) {
    uint32_t a;
    asm("{ .reg .u64 t; cvta.to.shared.u64 t, %1; cvt.u32.u64 %0, t; }"
        : "=r"(a) : "l"(p));
    return a;
}

__device__ __forceinline__ void cp16(uint32_t dst, const void* src) {
    asm volatile("cp.async.cg.shared.global [%0], [%1], 16;" :: "r"(dst), "l"(src));
}
#define CP_COMMIT() asm volatile("cp.async.commit_group;" ::: "memory")
#define CP_WAIT0()  asm volatile("cp.async.wait_group 0;" ::: "memory")

__device__ __forceinline__ void ldsm_x4(uint32_t addr, uint32_t& r0, uint32_t& r1,
                                        uint32_t& r2, uint32_t& r3) {
    asm volatile("ldmatrix.sync.aligned.m8n8.x4.shared.b16 {%0,%1,%2,%3}, [%4];"
        : "=r"(r0), "=r"(r1), "=r"(r2), "=r"(r3) : "r"(addr));
}

__device__ __forceinline__ void mma16832_h(uint32_t* d, const uint32_t* a, const uint32_t* b) {
    asm volatile("mma.sync.aligned.m16n8k32.row.col.f16.e4m3.e4m3.f16 "
        "{%0,%1}, {%2,%3,%4,%5}, {%6,%7}, {%0,%1};"
        : "+r"(d[0]), "+r"(d[1])
        : "r"(a[0]), "r"(a[1]), "r"(a[2]), "r"(a[3]), "r"(b[0]), "r"(b[1]));
}

__device__ __forceinline__ uint32_t sw_off(int row, int c16) {
    return (uint32_t)row * 128u + (uint32_t)((c16 ^ (row & 7)) * 16);
}

__device__ __forceinline__ __half2 u2h(uint32_t x) { __half2 h; *(uint32_t*)&h = x; return h; }
__device__ __forceinline__ uint32_t h2u(__half2 h) { return *(uint32_t*)&h; }

// top-3 packed-key insert (5 ops, branchless)
__device__ __forceinline__ void ins3(uint32_t k, uint32_t* v) {
    uint32_t a = min(v[0], k); v[0] = max(v[0], k);
    uint32_t b = min(v[1], a); v[1] = max(v[1], a);
    v[2] = max(v[2], b);
}

// exact fp32 top-3 insert (rescore only)
__device__ __forceinline__ void ins_tb3(float s, int gi,
    float& v0, int& i0, float& v1, int& i1, float& v2, int& i2) {
    bool b2 = (s > v2) || (s == v2 && gi < i2);
    if (!b2) return;
    bool b1 = (s > v1) || (s == v1 && gi < i1);
    if (b1) {
        bool b0 = (s > v0) || (s == v0 && gi < i0);
        if (b0) { v2=v1;i2=i1; v1=v0;i1=i0; v0=s;i0=gi; }
        else    { v2=v1;i2=i1; v1=s;i1=gi; }
    } else      { v2=s; i2=gi; }
}

// ---------------- fused prep kernel ----------------
__global__ void prep_kernel(const float* __restrict__ q, const float* __restrict__ m) {
    int w    = (blockIdx.x * blockDim.x + threadIdx.x) >> 5;
    int lane = threadIdx.x & 31;
    if (w < NQ) {
        float4 v = *(const float4*)(q + (size_t)w * D + lane * 4);
        float ss = v.x*v.x + v.y*v.y + v.z*v.z + v.w*v.w;
        #pragma unroll
        for (int o = 16; o; o >>= 1) ss += __shfl_xor_sync(0xffffffffu, ss, o);
        float inv = 1.0f / fmaxf(sqrtf(ss), 1e-12f);
        float4 r = { v.x*inv, v.y*inv, v.z*inv, v.w*inv };
        *(float4*)(g_qn + (size_t)w * D + lane * 4) = r;
        uint32_t lo = __nv_cvt_float2_to_fp8x2(make_float2(r.x, r.y), __NV_SATFINITE, __NV_E4M3);
        uint32_t hi = __nv_cvt_float2_to_fp8x2(make_float2(r.z, r.w), __NV_SATFINITE, __NV_E4M3);
        g_qf8[(size_t)w * 32 + lane] = (lo & 0xffffu) | (hi << 16);
    } else if (w < NQ + NM) {
        int row = w - NQ;
        float4 v = *(const float4*)(m + (size_t)row * D + lane * 4);
        float ss = v.x*v.x + v.y*v.y + v.z*v.z + v.w*v.w;
        #pragma unroll
        for (int o = 16; o; o >>= 1) ss += __shfl_xor_sync(0xffffffffu, ss, o);
        float inv = 1.0f / fmaxf(sqrtf(ss), 1e-12f);
        if (lane == 0) g_invm[row] = inv;
        float2 a = make_float2(v.x*inv, v.y*inv);
        float2 b = make_float2(v.z*inv, v.w*inv);
        uint32_t lo = __nv_cvt_float2_to_fp8x2(a, __NV_SATFINITE, __NV_E4M3);
        uint32_t hi = __nv_cvt_float2_to_fp8x2(b, __NV_SATFINITE, __NV_E4M3);
        g_mf8[(size_t)row * 32 + lane] = (lo & 0xffffu) | (hi << 16);
    }
}

__global__ void dummy_kernel(int v) { if (threadIdx.x == 1025) g_dummy = v; }

// ---- group extraction: 4 keys per slot -> top-3 list ----
__device__ __forceinline__ void extract_group(
    uint32_t gm[4], uint32_t gr2[4], uint32_t kv[4][3], int gbase, int colBase)
{
    int b0 = gbase + colBase;
    #pragma unroll
    for (int rs = 0; rs < 4; ++rs) {
        uint32_t A = gm[rs]  ^ 0x80008000u;
        uint32_t B = gr2[rs] ^ 0x80008000u;
        ins3((A << 16) | (uint32_t)(b0 + (int)((A & 0x33u) << 3)), kv[rs]);
        ins3((A & 0xFFFF0000u) | (uint32_t)(b0 + 1 + (int)(((A >> 16) & 0x33u) << 3)), kv[rs]);
        ins3((B << 16) | (uint32_t)(b0 + (int)((B & 0x33u) << 3)), kv[rs]);
        ins3((B & 0xFFFF0000u) | (uint32_t)(b0 + 1 + (int)(((B >> 16) & 0x33u) << 3)), kv[rs]);
        gm[rs] = 0xFC00FC00u; gr2[rs] = 0xFC00FC00u;
    }
}

// ---- full-tile epilogue: tournament + running 4-tile group merge ----
__device__ __forceinline__ void epi_full(
    const uint32_t acc[2][4][2], int tbase,
    uint32_t gm[4], uint32_t gr2[4], int& gcount, int& gbase,
    uint32_t kv[4][3], int colBase)
{
    if (gcount == 0) gbase = tbase;
    uint32_t cw = 0x00010001u * ((uint32_t)gcount << 4);
    #pragma unroll
    for (int mt = 0; mt < 2; ++mt)
        #pragma unroll
        for (int h = 0; h < 2; ++h) {
            const int rs = mt * 2 + h;
            uint32_t w0 = (acc[mt][0][h] & 0xFFCCFFCCu) | cw;
            uint32_t w1 = (acc[mt][1][h] & 0xFFCCFFCCu) | (cw + 0x00010001u);
            uint32_t w2 = (acc[mt][2][h] & 0xFFCCFFCCu) | (cw + 0x00020002u);
            uint32_t w3 = (acc[mt][3][h] & 0xFFCCFFCCu) | (cw + 0x00030003u);
            __half2 h0 = u2h(w0), h1 = u2h(w1), h2 = u2h(w2), h3 = u2h(w3);
            __half2 s1 = __hmax2(h0, h1), t1 = __hmin2(h0, h1);
            __half2 s2 = __hmax2(h2, h3), t2 = __hmin2(h2, h3);
            __half2 m1 = __hmax2(s1, s2);
            __half2 m2 = __hmax2(__hmin2(s1, s2), __hmax2(t1, t2));
            __half2 pm = u2h(gm[rs]), pr = u2h(gr2[rs]);
            __half2 f1 = __hmax2(pm, m1);
            __half2 f2 = __hmax2(__hmin2(pm, m1), __hmax2(pr, m2));
            gm[rs] = h2u(f1); gr2[rs] = h2u(f2);
        }
    if (++gcount == 4) {
        extract_group(gm, gr2, kv, gbase, colBase);
        gcount = 0;
    }
}

// ---- one pipeline stage: loads(t+1) + mma(t)->cur + epilogue(t-1 from prev) ----
__device__ __forceinline__ void tile_body(
    int t, int T, int mstart, int tid,
    uint32_t bSm, const char* mf8,
    uint32_t cur[2][4][2], const uint32_t prev[2][4][2],
    const uint32_t afr[4][2][4], const uint32_t boff[4][2],
    uint32_t gm[4], uint32_t gr2[4], int& gcount, int& gbase,
    uint32_t kv[4][3], int colBase)
{
    bool hn = (t + 1 < T);
    if (hn) {
        uint32_t bNext = bSm + ((t + 1) & 1) * B_BYTES;
        int row = tid >> 2;
        int c16b = (tid & 3) * 2;
        int gr = min(mstart + (t + 1) * NT + row, NM - 1);
        #pragma unroll
        for (int j = 0; j < 2; ++j)
            cp16(bNext + sw_off(row, c16b + j), mf8 + (size_t)gr * 128 + (c16b + j) * 16);
        CP_COMMIT();
    }

    uint32_t bB = bSm + (t & 1) * B_BYTES;

    #pragma unroll
    for (int mt = 0; mt < 2; ++mt)
        #pragma unroll
        for (int nt = 0; nt < 4; ++nt) {
            cur[mt][nt][0] = 0u;
            cur[mt][nt][1] = 0u;
        }

    #pragma unroll
    for (int kk = 0; kk < 4; ++kk) {
        uint32_t b[4][2];
        #pragma unroll
        for (int j = 0; j < 2; ++j)
            ldsm_x4(bB + boff[kk][j],
                    b[2*j][0], b[2*j][1], b[2*j+1][0], b[2*j+1][1]);
        #pragma unroll
        for (int mt = 0; mt < 2; ++mt)
            #pragma unroll
            for (int nt = 0; nt < 4; ++nt)
                mma16832_h(cur[mt][nt], afr[kk][mt], b[nt]);
    }

    // deferred epilogue for tile t-1 (phantom at t=0: prev = -inf/NaN, no-op)
    epi_full(prev, (t - 1) * NT, gm, gr2, gcount, gbase, kv, colBase);

    if (hn) CP_WAIT0();
    __syncthreads();
}

// ---- guarded flush for the (possibly partial) last tile ----
__device__ __forceinline__ void flush_last(
    const uint32_t acc[2][4][2], int t, int limit,
    uint32_t gm[4], uint32_t gr2[4], int& gcount, int& gbase,
    uint32_t kv[4][3], int colBase)
{
    if (t * NT + NT <= limit) {
        epi_full(acc, t * NT, gm, gr2, gcount, gbase, kv, colBase);
    } else {
        uint32_t lbase = (uint32_t)(t * NT + colBase);
        #pragma unroll
        for (int mt = 0; mt < 2; ++mt)
            #pragma unroll
            for (int h = 0; h < 2; ++h) {
                const int rs = mt * 2 + h;
                #pragma unroll
                for (int nt = 0; nt < 4; ++nt) {
                    uint32_t x  = acc[mt][nt][h] ^ 0x80008000u;
                    uint32_t i0 = lbase + nt * 8;
                    uint32_t k0 = (i0     < (uint32_t)limit) ? ((x << 16) | i0) : 0u;
                    uint32_t k1 = (i0 + 1 < (uint32_t)limit) ? ((x & 0xFFFF0000u) | (i0 + 1)) : 0u;
                    ins3(k0, kv[rs]);
                    ins3(k1, kv[rs]);
                }
            }
    }
    if (gcount > 0)
        extract_group(gm, gr2, kv, gbase, colBase);
}

// ---------------- main FP8 MMA (f16 acc), pipelined epilogue ----------------
__global__ __launch_bounds__(512, 1) void mma_topk_kernel() {
    extern __shared__ __align__(16) uint8_t dyn[];

    int tid  = threadIdx.x;
    int wid  = tid >> 5;
    int lane = tid & 31;
    int wm   = wid & 3;
    int wn   = wid >> 2;

    uint32_t raw  = s2u(dyn);
    uint32_t base = (raw + 1023u) & ~1023u;
    uint8_t* dbase = (uint8_t*)dyn + (base - raw);
    uint32_t aSm  = base;
    uint32_t bSm  = base + A_BYTES;

    int qbase  = blockIdx.x * QT;
    int chunk  = blockIdx.y;
    int mstart = chunk * CHUNK;
    int mend   = min(mstart + CHUNK, NM);
    int T      = (mend - mstart + NT - 1) / NT;
    int limit  = mend - mstart;

    const char* mf8 = (const char*)g_mf8;
    const char* qf8 = (const char*)g_qf8;

    // ---- prologue: A tile + B tile 0 ----
    {
        int row = tid >> 2;
        int c16a = (tid & 3) * 2;
        #pragma unroll
        for (int j = 0; j < 2; ++j)
            cp16(aSm + sw_off(row, c16a + j), qf8 + (size_t)(qbase + row) * 128 + (c16a + j) * 16);
        int gr = min(mstart + row, NM - 1);
        #pragma unroll
        for (int j = 0; j < 2; ++j)
            cp16(bSm + sw_off(row, c16a + j), mf8 + (size_t)gr * 128 + (c16a + j) * 16);
    }
    CP_COMMIT();
    CP_WAIT0();
    __syncthreads();

    // ---- hoist A fragments ----
    int rowA0 = wm * 32 + (lane & 15);
    int hiA   = lane >> 4;
    uint32_t afr[4][2][4];
    #pragma unroll
    for (int kk = 0; kk < 4; ++kk)
        #pragma unroll
        for (int mt = 0; mt < 2; ++mt)
            ldsm_x4(aSm + sw_off(rowA0 + mt * 16, 2 * kk + hiA),
                    afr[kk][mt][0], afr[kk][mt][1], afr[kk][mt][2], afr[kk][mt][3]);

    // ---- hoist B ldsm swizzle offsets ----
    int grp   = lane >> 3;
    int rowB0 = wn * 32 + (lane & 7) + (grp >> 1) * 8;
    int hiB   = grp & 1;
    uint32_t boff[4][2];
    #pragma unroll
    for (int kk = 0; kk < 4; ++kk)
        #pragma unroll
        for (int j = 0; j < 2; ++j)
            boff[kk][j] = sw_off(rowB0 + j * 16, 2 * kk + hiB);

    uint32_t kv[4][3];
    uint32_t gm[4], gr2[4];
    uint32_t accA[2][4][2], accB[2][4][2];
    #pragma unroll
    for (int r = 0; r < 4; ++r) {
        kv[r][0] = kv[r][1] = kv[r][2] = 0u;
        gm[r] = 0xFC00FC00u; gr2[r] = 0xFC00FC00u;
    }
    #pragma unroll
    for (int mt = 0; mt < 2; ++mt)
        #pragma unroll
        for (int nt = 0; nt < 4; ++nt) {
            accB[mt][nt][0] = 0xFC00FC00u;   // phantom prev for t=0
            accB[mt][nt][1] = 0xFC00FC00u;
        }

    int gcount = 0, gbase = 0;
    int colBase = wn * 32 + (lane & 3) * 2;

    // ---- main loop, unrolled x2 for acc double-buffering ----
    for (int t2 = 0; t2 < T; t2 += 2) {
        tile_body(t2, T, mstart, tid, bSm, mf8, accA, accB,
                  afr, boff, gm, gr2, gcount, gbase, kv, colBase);
        if (t2 + 1 < T)
            tile_body(t2 + 1, T, mstart, tid, bSm, mf8, accB, accA,
                      afr, boff, gm, gr2, gcount, gbase, kv, colBase);
    }

    // ---- flush last tile (epilogue deferred from loop) ----
    if ((T - 1) & 1)
        flush_last(accB, T - 1, limit, gm, gr2, gcount, gbase, kv, colBase);
    else
        flush_last(accA, T - 1, limit, gm, gr2, gcount, gbase, kv, colBase);

    // ---- merge across the 4 lanes sharing each row (xor 1, 2) ----
    #pragma unroll
    for (int off = 1; off <= 2; off <<= 1) {
        #pragma unroll
        for (int rs = 0; rs < 4; ++rs) {
            uint32_t o0 = __shfl_xor_sync(0xffffffffu, kv[rs][0], off);
            uint32_t o1 = __shfl_xor_sync(0xffffffffu, kv[rs][1], off);
            uint32_t o2 = __shfl_xor_sync(0xffffffffu, kv[rs][2], off);
            ins3(o0, kv[rs]);
            ins3(o1, kv[rs]);
            ins3(o2, kv[rs]);
        }
    }
    __syncthreads();

    // ---- cross-warp_n merge via smem: [4 wn][128 rows][3 keys] ----
    uint32_t* smk = (uint32_t*)dbase;           // 6 KB
    if ((lane & 3) == 0) {
        #pragma unroll
        for (int rs = 0; rs < 4; ++rs) {
            int row = wm * 32 + (rs >> 1) * 16 + (lane >> 2) + (rs & 1) * 8;
            int o = (wn * 128 + row) * 3;
            smk[o+0] = kv[rs][0];
            smk[o+1] = kv[rs][1];
            smk[o+2] = kv[rs][2];
        }
    }
    __syncthreads();
    if (tid < 128) {
        int row = tid;
        uint32_t ak[12];
        #pragma unroll
        for (int seg = 0; seg < 4; ++seg)
            #pragma unroll
            for (int j = 0; j < 3; ++j)
                ak[seg*3+j] = smk[(seg * 128 + row) * 3 + j];
        size_t cb = ((size_t)(qbase + row) * NCH + chunk) * KC;
        #pragma unroll
        for (int s = 0; s < KC; ++s) {
            int best = s;
            for (int j = s + 1; j < 12; ++j)
                if (ak[j] > ak[best]) best = j;
            uint32_t bk = ak[best];
            ak[best] = ak[s];
            ak[s] = bk;
            g_ci[cb + s] = mstart + (int)(bk & 0xFFFFu);
        }
    }
}

// ---------------- exact fp32 rescore + final top-3 ----------------
__global__ void rescore_kernel(const float* __restrict__ mem, float* __restrict__ out) {
    __shared__ float sv[8][3];
    __shared__ int   si[8][3];

    int tid  = threadIdx.x;
    int wid  = tid >> 5;
    int lane = tid & 31;
    int qidx = blockIdx.x;

    float4 qv = *(const float4*)(g_qn + (size_t)qidx * D + lane * 4);

    float v0 = -2.f, v1 = -2.f, v2 = -2.f;
    int   i0 = 0x7fffffff, i1 = 0x7fffffff, i2 = 0x7fffffff;

    size_t cb = (size_t)qidx * NCH * KC;
    #pragma unroll 1
    for (int j = wid; j < NCH * KC; j += 8) {
        int gi = g_ci[cb + j];
        if ((unsigned)gi >= (unsigned)NM) continue;
        float4 mv = *(const float4*)(mem + (size_t)gi * D + lane * 4);
        float s = qv.x*mv.x + qv.y*mv.y + qv.z*mv.z + qv.w*mv.w;
        #pragma unroll
        for (int o = 16; o; o >>= 1) s += __shfl_xor_sync(0xffffffffu, s, o);
        s *= g_invm[gi];
        ins_tb3(s, gi, v0, i0, v1, i1, v2, i2);
    }
    if (lane == 0) {
        sv[wid][0]=v0; si[wid][0]=i0;
        sv[wid][1]=v1; si[wid][1]=i1;
        sv[wid][2]=v2; si[wid][2]=i2;
    }
    __syncthreads();

    if (tid == 0) {
        float w0 = -2.f, w1 = -2.f, w2 = -2.f;
        int   a0 = 0x7fffffff, a1 = 0x7fffffff, a2 = 0x7fffffff;
        #pragma unroll
        for (int p = 0; p < 8; ++p)
            #pragma unroll
            for (int j = 0; j < 3; ++j)
                ins_tb3(sv[p][j], si[p][j], w0,a0, w1,a1, w2,a2);
        out[(size_t)qidx * 3 + 0] = 1.0f - w0;
        out[(size_t)qidx * 3 + 1] = 1.0f - w1;
        out[(size_t)qidx * 3 + 2] = 1.0f - w2;
        out[(size_t)NQ * 3 + (size_t)qidx * 3 + 0] = (float)a0;
        out[(size_t)NQ * 3 + (size_t)qidx * 3 + 1] = (float)a1;
        out[(size_t)NQ * 3 + (size_t)qidx * 3 + 2] = (float)a2;
    }
}

// ---------------- launch ----------------
extern "C" void kernel_launch(void* const* d_in, const int* in_sizes, int n_in,
                              void* d_out, int out_size) {
    const float* q   = (const float*)d_in[0];
    const float* mem = (const float*)d_in[1];
    float* out = (float*)d_out;

    cudaFuncSetAttribute(mma_topk_kernel,
                         cudaFuncAttributeMaxDynamicSharedMemorySize, SMEM_DYN);

    int prep_warps = NQ + NM;
    prep_kernel<<<(prep_warps * 32 + 255) / 256, 256>>>(q, mem);
    dummy_kernel<<<1, 32>>>(1);
    dummy_kernel<<<1, 32>>>(2);

    dim3 grid(NQ / QT, NCH);
    mma_topk_kernel<<<grid, 512, SMEM_DYN>>>();

    rescore_kernel<<<NQ, 256>>>(mem, out);
}

// round 16
// speedup vs baseline: 1.1150x; 1.1150x over previous
#include <cuda_runtime.h>
#include <cuda_fp8.h>
#include <cuda_fp16.h>
#include <cstdint>
#include <math.h>

// ---------------- problem constants ----------------
#define NQ     4096
#define NM     100000
#define D      128
#define NCH    37
#define CHUNK  2703          // ceil(NM / NCH)
#define QT     128           // queries per CTA (block M)
#define NT     128           // memory rows per tile (block N)
#define KC     8             // candidates kept per (query, chunk)

#define A_BYTES   (QT * D)              // fp8: 16384
#define B_BYTES   (NT * D)              // 16384
#define SMEM_DYN  (A_BYTES + 2 * B_BYTES + 1024)   // ~50KB

// ---------------- device scratch ----------------
__device__ float     g_qn[NQ * D];        // normalized queries (fp32)
__device__ uint32_t  g_qf8[NQ * 32];      // normalized queries (e4m3, 4/word)
__device__ uint32_t  g_mf8[NM * 32];      // normalized memory (e4m3)
__device__ float     g_invm[NM];          // 1/||m||
__device__ int       g_ci[NQ * NCH * KC];
__device__ int       g_dummy;

// ---------------- PTX helpers ----------------
__device__ __forceinline__ uint32_t s2u(const void* p) {
    uint32_t a;
    asm("{ .reg .u64 t; cvta.to.shared.u64 t, %1; cvt.u32.u64 %0, t; }"
        : "=r"(a) : "l"(p));
    return a;
}

__device__ __forceinline__ void cp16(uint32_t dst, const void* src) {
    asm volatile("cp.async.cg.shared.global [%0], [%1], 16;" :: "r"(dst), "l"(src));
}
#define CP_COMMIT() asm volatile("cp.async.commit_group;" ::: "memory")
#define CP_WAIT0()  asm volatile("cp.async.wait_group 0;" ::: "memory")

__device__ __forceinline__ void ldsm_x4(uint32_t addr, uint32_t& r0, uint32_t& r1,
                                        uint32_t& r2, uint32_t& r3) {
    asm volatile("ldmatrix.sync.aligned.m8n8.x4.shared.b16 {%0,%1,%2,%3}, [%4];"
        : "=r"(r0), "=r"(r1), "=r"(r2), "=r"(r3) : "r"(addr));
}

__device__ __forceinline__ void mma16832_h(uint32_t* d, const uint32_t* a, const uint32_t* b) {
    asm volatile("mma.sync.aligned.m16n8k32.row.col.f16.e4m3.e4m3.f16 "
        "{%0,%1}, {%2,%3,%4,%5}, {%6,%7}, {%0,%1};"
        : "+r"(d[0]), "+r"(d[1])
        : "r"(a[0]), "r"(a[1]), "r"(a[2]), "r"(a[3]), "r"(b[0]), "r"(b[1]));
}

__device__ __forceinline__ uint32_t sw_off(int row, int c16) {
    return (uint32_t)row * 128u + (uint32_t)((c16 ^ (row & 7)) * 16);
}

__device__ __forceinline__ __half2 u2h(uint32_t x) { __half2 h; *(uint32_t*)&h = x; return h; }
__device__ __forceinline__ uint32_t h2u(__half2 h) { return *(uint32_t*)&h; }

// top-3 packed-key insert (5 ops, branchless)
__device__ __forceinline__ void ins3(uint32_t k, uint32_t* v) {
    uint32_t a = min(v[0], k); v[0] = max(v[0], k);
    uint32_t b = min(v[1], a); v[1] = max(v[1], a);
    v[2] = max(v[2], b);
}

// exact fp32 top-3 insert (rescore only)
__device__ __forceinline__ void ins_tb3(float s, int gi,
    float& v0, int& i0, float& v1, int& i1, float& v2, int& i2) {
    bool b2 = (s > v2) || (s == v2 && gi < i2);
    if (!b2) return;
    bool b1 = (s > v1) || (s == v1 && gi < i1);
    if (b1) {
        bool b0 = (s > v0) || (s == v0 && gi < i0);
        if (b0) { v2=v1;i2=i1; v1=v0;i1=i0; v0=s;i0=gi; }
        else    { v2=v1;i2=i1; v1=s;i1=gi; }
    } else      { v2=s; i2=gi; }
}

// ---------------- fused prep kernel ----------------
__global__ void prep_kernel(const float* __restrict__ q, const float* __restrict__ m) {
    int w    = (blockIdx.x * blockDim.x + threadIdx.x) >> 5;
    int lane = threadIdx.x & 31;
    if (w < NQ) {
        float4 v = *(const float4*)(q + (size_t)w * D + lane * 4);
        float ss = v.x*v.x + v.y*v.y + v.z*v.z + v.w*v.w;
        #pragma unroll
        for (int o = 16; o; o >>= 1) ss += __shfl_xor_sync(0xffffffffu, ss, o);
        float inv = 1.0f / fmaxf(sqrtf(ss), 1e-12f);
        float4 r = { v.x*inv, v.y*inv, v.z*inv, v.w*inv };
        *(float4*)(g_qn + (size_t)w * D + lane * 4) = r;
        uint32_t lo = __nv_cvt_float2_to_fp8x2(make_float2(r.x, r.y), __NV_SATFINITE, __NV_E4M3);
        uint32_t hi = __nv_cvt_float2_to_fp8x2(make_float2(r.z, r.w), __NV_SATFINITE, __NV_E4M3);
        g_qf8[(size_t)w * 32 + lane] = (lo & 0xffffu) | (hi << 16);
    } else if (w < NQ + NM) {
        int row = w - NQ;
        float4 v = *(const float4*)(m + (size_t)row * D + lane * 4);
        float ss = v.x*v.x + v.y*v.y + v.z*v.z + v.w*v.w;
        #pragma unroll
        for (int o = 16; o; o >>= 1) ss += __shfl_xor_sync(0xffffffffu, ss, o);
        float inv = 1.0f / fmaxf(sqrtf(ss), 1e-12f);
        if (lane == 0) g_invm[row] = inv;
        float2 a = make_float2(v.x*inv, v.y*inv);
        float2 b = make_float2(v.z*inv, v.w*inv);
        uint32_t lo = __nv_cvt_float2_to_fp8x2(a, __NV_SATFINITE, __NV_E4M3);
        uint32_t hi = __nv_cvt_float2_to_fp8x2(b, __NV_SATFINITE, __NV_E4M3);
        g_mf8[(size_t)row * 32 + lane] = (lo & 0xffffu) | (hi << 16);
    }
}

__global__ void dummy_kernel(int v) { if (threadIdx.x == 1025) g_dummy = v; }

// ---- group extraction: 4 keys per slot -> top-3 list ----
__device__ __forceinline__ void extract_group(
    uint32_t gm[4], uint32_t gr2[4], uint32_t kv[4][3], int gbase, int colBase)
{
    int b0 = gbase + colBase;
    #pragma unroll
    for (int rs = 0; rs < 4; ++rs) {
        uint32_t A = gm[rs]  ^ 0x80008000u;
        uint32_t B = gr2[rs] ^ 0x80008000u;
        ins3((A << 16) | (uint32_t)(b0 + (int)((A & 0x33u) << 3)), kv[rs]);
        ins3((A & 0xFFFF0000u) | (uint32_t)(b0 + 1 + (int)(((A >> 16) & 0x33u) << 3)), kv[rs]);
        ins3((B << 16) | (uint32_t)(b0 + (int)((B & 0x33u) << 3)), kv[rs]);
        ins3((B & 0xFFFF0000u) | (uint32_t)(b0 + 1 + (int)(((B >> 16) & 0x33u) << 3)), kv[rs]);
        gm[rs] = 0xFC00FC00u; gr2[rs] = 0xFC00FC00u;
    }
}

// ---- full-tile epilogue: tournament + running 4-tile group merge ----
__device__ __forceinline__ void epi_full(
    const uint32_t acc[2][4][2], int tbase,
    uint32_t gm[4], uint32_t gr2[4], int& gcount, int& gbase,
    uint32_t kv[4][3], int colBase)
{
    if (gcount == 0) gbase = tbase;
    uint32_t cw = 0x00010001u * ((uint32_t)gcount << 4);
    #pragma unroll
    for (int mt = 0; mt < 2; ++mt)
        #pragma unroll
        for (int h = 0; h < 2; ++h) {
            const int rs = mt * 2 + h;
            uint32_t w0 = (acc[mt][0][h] & 0xFFCCFFCCu) | cw;
            uint32_t w1 = (acc[mt][1][h] & 0xFFCCFFCCu) | (cw + 0x00010001u);
            uint32_t w2 = (acc[mt][2][h] & 0xFFCCFFCCu) | (cw + 0x00020002u);
            uint32_t w3 = (acc[mt][3][h] & 0xFFCCFFCCu) | (cw + 0x00030003u);
            __half2 h0 = u2h(w0), h1 = u2h(w1), h2 = u2h(w2), h3 = u2h(w3);
            __half2 s1 = __hmax2(h0, h1), t1 = __hmin2(h0, h1);
            __half2 s2 = __hmax2(h2, h3), t2 = __hmin2(h2, h3);
            __half2 m1 = __hmax2(s1, s2);
            __half2 m2 = __hmax2(__hmin2(s1, s2), __hmax2(t1, t2));
            __half2 pm = u2h(gm[rs]), pr = u2h(gr2[rs]);
            __half2 f1 = __hmax2(pm, m1);
            __half2 f2 = __hmax2(__hmin2(pm, m1), __hmax2(pr, m2));
            gm[rs] = h2u(f1); gr2[rs] = h2u(f2);
        }
    if (++gcount == 4) {
        extract_group(gm, gr2, kv, gbase, colBase);
        gcount = 0;
    }
}

// ---- one pipeline stage: loads(t+1) + mma(t)->cur + epilogue(t-1 from prev) ----
// A fragments are re-loaded from smem each k-step (frees 32 regs vs hoisting).
__device__ __forceinline__ void tile_body(
    int t, int T, int mstart, int tid,
    uint32_t bSm, const char* mf8,
    uint32_t cur[2][4][2], const uint32_t prev[2][4][2],
    const uint32_t aoff[4][2], const uint32_t boff[4][2],
    uint32_t gm[4], uint32_t gr2[4], int& gcount, int& gbase,
    uint32_t kv[4][3], int colBase)
{
    bool hn = (t + 1 < T);
    if (hn) {
        uint32_t bNext = bSm + ((t + 1) & 1) * B_BYTES;
        int row = tid >> 2;
        int c16b = (tid & 3) * 2;
        int gr = min(mstart + (t + 1) * NT + row, NM - 1);
        #pragma unroll
        for (int j = 0; j < 2; ++j)
            cp16(bNext + sw_off(row, c16b + j), mf8 + (size_t)gr * 128 + (c16b + j) * 16);
        CP_COMMIT();
    }

    uint32_t bB = bSm + (t & 1) * B_BYTES;

    #pragma unroll
    for (int mt = 0; mt < 2; ++mt)
        #pragma unroll
        for (int nt = 0; nt < 4; ++nt) {
            cur[mt][nt][0] = 0u;
            cur[mt][nt][1] = 0u;
        }

    #pragma unroll
    for (int kk = 0; kk < 4; ++kk) {
        uint32_t a[2][4];
        #pragma unroll
        for (int mt = 0; mt < 2; ++mt)
            ldsm_x4(aoff[kk][mt], a[mt][0], a[mt][1], a[mt][2], a[mt][3]);
        uint32_t b[4][2];
        #pragma unroll
        for (int j = 0; j < 2; ++j)
            ldsm_x4(bB + boff[kk][j],
                    b[2*j][0], b[2*j][1], b[2*j+1][0], b[2*j+1][1]);
        #pragma unroll
        for (int mt = 0; mt < 2; ++mt)
            #pragma unroll
            for (int nt = 0; nt < 4; ++nt)
                mma16832_h(cur[mt][nt], a[mt], b[nt]);
    }

    // deferred epilogue for tile t-1 (phantom at t=0: prev = -inf, no-op)
    epi_full(prev, (t - 1) * NT, gm, gr2, gcount, gbase, kv, colBase);

    if (hn) CP_WAIT0();
    __syncthreads();
}

// ---- guarded flush for the (possibly partial) last tile ----
__device__ __forceinline__ void flush_last(
    const uint32_t acc[2][4][2], int t, int limit,
    uint32_t gm[4], uint32_t gr2[4], int& gcount, int& gbase,
    uint32_t kv[4][3], int colBase)
{
    if (t * NT + NT <= limit) {
        epi_full(acc, t * NT, gm, gr2, gcount, gbase, kv, colBase);
    } else {
        uint32_t lbase = (uint32_t)(t * NT + colBase);
        #pragma unroll
        for (int mt = 0; mt < 2; ++mt)
            #pragma unroll
            for (int h = 0; h < 2; ++h) {
                const int rs = mt * 2 + h;
                #pragma unroll
                for (int nt = 0; nt < 4; ++nt) {
                    uint32_t x  = acc[mt][nt][h] ^ 0x80008000u;
                    uint32_t i0 = lbase + nt * 8;
                    uint32_t k0 = (i0     < (uint32_t)limit) ? ((x << 16) | i0) : 0u;
                    uint32_t k1 = (i0 + 1 < (uint32_t)limit) ? ((x & 0xFFFF0000u) | (i0 + 1)) : 0u;
                    ins3(k0, kv[rs]);
                    ins3(k1, kv[rs]);
                }
            }
    }
    if (gcount > 0)
        extract_group(gm, gr2, kv, gbase, colBase);
}

// ---------------- main FP8 MMA (f16 acc), pipelined epilogue ----------------
__global__ __launch_bounds__(512, 1) void mma_topk_kernel() {
    extern __shared__ __align__(16) uint8_t dyn[];

    int tid  = threadIdx.x;
    int wid  = tid >> 5;
    int lane = tid & 31;
    int wm   = wid & 3;
    int wn   = wid >> 2;

    uint32_t raw  = s2u(dyn);
    uint32_t base = (raw + 1023u) & ~1023u;
    uint8_t* dbase = (uint8_t*)dyn + (base - raw);
    uint32_t aSm  = base;
    uint32_t bSm  = base + A_BYTES;

    int qbase  = blockIdx.x * QT;
    int chunk  = blockIdx.y;
    int mstart = chunk * CHUNK;
    int mend   = min(mstart + CHUNK, NM);
    int T      = (mend - mstart + NT - 1) / NT;
    int limit  = mend - mstart;

    const char* mf8 = (const char*)g_mf8;
    const char* qf8 = (const char*)g_qf8;

    // ---- prologue: A tile + B tile 0 ----
    {
        int row = tid >> 2;
        int c16a = (tid & 3) * 2;
        #pragma unroll
        for (int j = 0; j < 2; ++j)
            cp16(aSm + sw_off(row, c16a + j), qf8 + (size_t)(qbase + row) * 128 + (c16a + j) * 16);
        int gr = min(mstart + row, NM - 1);
        #pragma unroll
        for (int j = 0; j < 2; ++j)
            cp16(bSm + sw_off(row, c16a + j), mf8 + (size_t)gr * 128 + (c16a + j) * 16);
    }
    CP_COMMIT();
    CP_WAIT0();
    __syncthreads();

    // ---- hoist A ldsm addresses (8 regs; fragments re-loaded per tile) ----
    int rowA0 = wm * 32 + (lane & 15);
    int hiA   = lane >> 4;
    uint32_t aoff[4][2];
    #pragma unroll
    for (int kk = 0; kk < 4; ++kk)
        #pragma unroll
        for (int mt = 0; mt < 2; ++mt)
            aoff[kk][mt] = aSm + sw_off(rowA0 + mt * 16, 2 * kk + hiA);

    // ---- hoist B ldsm swizzle offsets ----
    int grp   = lane >> 3;
    int rowB0 = wn * 32 + (lane & 7) + (grp >> 1) * 8;
    int hiB   = grp & 1;
    uint32_t boff[4][2];
    #pragma unroll
    for (int kk = 0; kk < 4; ++kk)
        #pragma unroll
        for (int j = 0; j < 2; ++j)
            boff[kk][j] = sw_off(rowB0 + j * 16, 2 * kk + hiB);

    uint32_t kv[4][3];
    uint32_t gm[4], gr2[4];
    uint32_t accA[2][4][2], accB[2][4][2];
    #pragma unroll
    for (int r = 0; r < 4; ++r) {
        kv[r][0] = kv[r][1] = kv[r][2] = 0u;
        gm[r] = 0xFC00FC00u; gr2[r] = 0xFC00FC00u;
    }
    #pragma unroll
    for (int mt = 0; mt < 2; ++mt)
        #pragma unroll
        for (int nt = 0; nt < 4; ++nt) {
            accB[mt][nt][0] = 0xFC00FC00u;   // phantom prev for t=0
            accB[mt][nt][1] = 0xFC00FC00u;
        }

    int gcount = 0, gbase = 0;
    int colBase = wn * 32 + (lane & 3) * 2;

    // ---- main loop, unrolled x2 for acc double-buffering ----
    for (int t2 = 0; t2 < T; t2 += 2) {
        tile_body(t2, T, mstart, tid, bSm, mf8, accA, accB,
                  aoff, boff, gm, gr2, gcount, gbase, kv, colBase);
        if (t2 + 1 < T)
            tile_body(t2 + 1, T, mstart, tid, bSm, mf8, accB, accA,
                      aoff, boff, gm, gr2, gcount, gbase, kv, colBase);
    }

    // ---- flush last tile (epilogue deferred from loop) ----
    if ((T - 1) & 1)
        flush_last(accB, T - 1, limit, gm, gr2, gcount, gbase, kv, colBase);
    else
        flush_last(accA, T - 1, limit, gm, gr2, gcount, gbase, kv, colBase);

    // ---- merge across the 4 lanes sharing each row (xor 1, 2) ----
    #pragma unroll
    for (int off = 1; off <= 2; off <<= 1) {
        #pragma unroll
        for (int rs = 0; rs < 4; ++rs) {
            uint32_t o0 = __shfl_xor_sync(0xffffffffu, kv[rs][0], off);
            uint32_t o1 = __shfl_xor_sync(0xffffffffu, kv[rs][1], off);
            uint32_t o2 = __shfl_xor_sync(0xffffffffu, kv[rs][2], off);
            ins3(o0, kv[rs]);
            ins3(o1, kv[rs]);
            ins3(o2, kv[rs]);
        }
    }
    __syncthreads();

    // ---- cross-warp_n merge via smem: [4 wn][128 rows][3 keys] ----
    uint32_t* smk = (uint32_t*)dbase;           // 6 KB
    if ((lane & 3) == 0) {
        #pragma unroll
        for (int rs = 0; rs < 4; ++rs) {
            int row = wm * 32 + (rs >> 1) * 16 + (lane >> 2) + (rs & 1) * 8;
            int o = (wn * 128 + row) * 3;
            smk[o+0] = kv[rs][0];
            smk[o+1] = kv[rs][1];
            smk[o+2] = kv[rs][2];
        }
    }
    __syncthreads();
    if (tid < 128) {
        int row = tid;
        uint32_t ak[12];
        #pragma unroll
        for (int seg = 0; seg < 4; ++seg)
            #pragma unroll
            for (int j = 0; j < 3; ++j)
                ak[seg*3+j] = smk[(seg * 128 + row) * 3 + j];
        size_t cb = ((size_t)(qbase + row) * NCH + chunk) * KC;
        #pragma unroll
        for (int s = 0; s < KC; ++s) {
            int best = s;
            for (int j = s + 1; j < 12; ++j)
                if (ak[j] > ak[best]) best = j;
            uint32_t bk = ak[best];
            ak[best] = ak[s];
            ak[s] = bk;
            g_ci[cb + s] = mstart + (int)(bk & 0xFFFFu);
        }
    }
}

// ---------------- exact fp32 rescore + final top-3 ----------------
__global__ void rescore_kernel(const float* __restrict__ mem, float* __restrict__ out) {
    __shared__ float sv[8][3];
    __shared__ int   si[8][3];

    int tid  = threadIdx.x;
    int wid  = tid >> 5;
    int lane = tid & 31;
    int qidx = blockIdx.x;

    float4 qv = *(const float4*)(g_qn + (size_t)qidx * D + lane * 4);

    float v0 = -2.f, v1 = -2.f, v2 = -2.f;
    int   i0 = 0x7fffffff, i1 = 0x7fffffff, i2 = 0x7fffffff;

    size_t cb = (size_t)qidx * NCH * KC;
    #pragma unroll 1
    for (int j = wid; j < NCH * KC; j += 8) {
        int gi = g_ci[cb + j];
        if ((unsigned)gi >= (unsigned)NM) continue;
        float4 mv = *(const float4*)(mem + (size_t)gi * D + lane * 4);
        float s = qv.x*mv.x + qv.y*mv.y + qv.z*mv.z + qv.w*mv.w;
        #pragma unroll
        for (int o = 16; o; o >>= 1) s += __shfl_xor_sync(0xffffffffu, s, o);
        s *= g_invm[gi];
        ins_tb3(s, gi, v0, i0, v1, i1, v2, i2);
    }
    if (lane == 0) {
        sv[wid][0]=v0; si[wid][0]=i0;
        sv[wid][1]=v1; si[wid][1]=i1;
        sv[wid][2]=v2; si[wid][2]=i2;
    }
    __syncthreads();

    if (tid == 0) {
        float w0 = -2.f, w1 = -2.f, w2 = -2.f;
        int   a0 = 0x7fffffff, a1 = 0x7fffffff, a2 = 0x7fffffff;
        #pragma unroll
        for (int p = 0; p < 8; ++p)
            #pragma unroll
            for (int j = 0; j < 3; ++j)
                ins_tb3(sv[p][j], si[p][j], w0,a0, w1,a1, w2,a2);
        out[(size_t)qidx * 3 + 0] = 1.0f - w0;
        out[(size_t)qidx * 3 + 1] = 1.0f - w1;
        out[(size_t)qidx * 3 + 2] = 1.0f - w2;
        out[(size_t)NQ * 3 + (size_t)qidx * 3 + 0] = (float)a0;
        out[(size_t)NQ * 3 + (size_t)qidx * 3 + 1] = (float)a1;
        out[(size_t)NQ * 3 + (size_t)qidx * 3 + 2] = (float)a2;
    }
}

// ---------------- launch ----------------
extern "C" void kernel_launch(void* const* d_in, const int* in_sizes, int n_in,
                              void* d_out, int out_size) {
    const float* q   = (const float*)d_in[0];
    const float* mem = (const float*)d_in[1];
    float* out = (float*)d_out;

    cudaFuncSetAttribute(mma_topk_kernel,
                         cudaFuncAttributeMaxDynamicSharedMemorySize, SMEM_DYN);

    int prep_warps = NQ + NM;
    prep_kernel<<<(prep_warps * 32 + 255) / 256, 256>>>(q, mem);
    dummy_kernel<<<1, 32>>>(1);
    dummy_kernel<<<1, 32>>>(2);

    dim3 grid(NQ / QT, NCH);
    mma_topk_kernel<<<grid, 512, SMEM_DYN>>>();

    rescore_kernel<<<NQ, 256>>>(mem, out);
}